// round 1
// baseline (speedup 1.0000x reference)
#include <cuda_runtime.h>
#include <cstdint>
#include <cstddef>

// Problem constants
#define T_STEPS   101
#define B_SZ      16384
#define IN_DIM    40
#define HID       300
#define NPAD      320         // HID padded to multiple of 32
#define NJ        10          // NPAD / 32
#define OUT_DIM   12

#define WARPS_PER_BLK   16
#define THREADS_PER_BLK (WARPS_PER_BLK * 32)
#define NUM_BLKS        (B_SZ / WARPS_PER_BLK)   // 1024
#define AL_STRIDE       304                      // active-list capacity per row (u16)

// Transposed, padded weight scratch (shared by all blocks, L2-resident: 384KB each)
__device__ float g_WhT[HID * NPAD];   // g_WhT[k*NPAD + i] = Wh[i*HID + k]
__device__ float g_W2T[HID * NPAD];   // g_W2T[k*NPAD + i] = W2[i*HID + k]

__global__ void prep_kernel(const float* __restrict__ Wh,
                            const float* __restrict__ W2) {
    int idx = blockIdx.x * blockDim.x + threadIdx.x;
    const int total = HID * NPAD;
    if (idx < total) {
        int k = idx / NPAD;
        int i = idx % NPAD;
        float wh = 0.0f, w2 = 0.0f;
        if (i < HID) {
            wh = Wh[i * HID + k];
            w2 = W2[i * HID + k];
        }
        g_WhT[idx] = wh;
        g_W2T[idx] = w2;
    }
}

// Persistent SNN kernel: one warp owns one batch row for all T steps.
// v1, v2 live in registers (10 lanes-slices each), spikes tracked as a
// per-row active-index list in shared memory (binary spikes -> gather-add,
// products exact in fp32).
__global__ void __launch_bounds__(THREADS_PER_BLK, 2)
snn_kernel(const float* __restrict__ x,
           const float* __restrict__ W1,
           const float* __restrict__ b1,
           const float* __restrict__ bh,
           const float* __restrict__ b2,
           const float* __restrict__ W3,
           const float* __restrict__ b3,
           float* __restrict__ out) {
    extern __shared__ char smem_raw[];
    float* W1Ts = (float*)smem_raw;                       // [IN_DIM][NPAD]
    float* W3Ts = W1Ts + IN_DIM * NPAD;                   // [NPAD][OUT_DIM]
    float* bsum = W3Ts + NPAD * OUT_DIM;                  // [NPAD]  (b1 + bh)
    float* b2s  = bsum + NPAD;                            // [NPAD]
    float* b3s  = b2s + NPAD;                             // [16]
    unsigned short* al = (unsigned short*)(b3s + 16);     // [WARPS_PER_BLK][AL_STRIDE]

    const int tid = threadIdx.x;

    // ---- cooperative smem init ----
    for (int idx = tid; idx < IN_DIM * NPAD; idx += THREADS_PER_BLK) {
        int k = idx / NPAD;
        int h = idx % NPAD;
        W1Ts[idx] = (h < HID) ? W1[h * IN_DIM + k] : 0.0f;
    }
    for (int idx = tid; idx < NPAD * OUT_DIM; idx += THREADS_PER_BLK) {
        int n = idx / OUT_DIM;
        int o = idx % OUT_DIM;
        W3Ts[idx] = (n < HID) ? W3[o * HID + n] : 0.0f;
    }
    for (int n = tid; n < NPAD; n += THREADS_PER_BLK) {
        bsum[n] = (n < HID) ? (b1[n] + bh[n]) : 0.0f;
        b2s[n]  = (n < HID) ? b2[n] : 0.0f;
    }
    if (tid < OUT_DIM) b3s[tid] = b3[tid];
    __syncthreads();

    const int w   = tid >> 5;
    const int L   = tid & 31;
    const int row = blockIdx.x * WARPS_PER_BLK + w;
    unsigned short* alr = al + w * AL_STRIDE;

    // LIF states in registers: neuron n = L + 32*j
    float v1[NJ], v2[NJ];
#pragma unroll
    for (int j = 0; j < NJ; j++) { v1[j] = 0.0f; v2[j] = 0.0f; }
    float outacc = 0.0f;
    int cnt = 0;   // warp-uniform active-spike count

#pragma unroll 1
    for (int t = 0; t < T_STEPS; t++) {
        // ================= layer 1 current =================
        float cur[NJ];
#pragma unroll
        for (int j = 0; j < NJ; j++) cur[j] = bsum[L + 32 * j];

        // dense input part: cur += x_t[row] @ W1.T  (K = 40, W1T in smem)
        const float* xr = x + ((size_t)t * B_SZ + row) * IN_DIM;
        float xa = xr[L];
        float xb = (L < 8) ? xr[32 + L] : 0.0f;
#pragma unroll 4
        for (int k = 0; k < 32; k++) {
            float xv = __shfl_sync(0xffffffffu, xa, k);
            const float* wr = W1Ts + k * NPAD + L;
#pragma unroll
            for (int j = 0; j < NJ; j++) cur[j] += xv * wr[32 * j];
        }
#pragma unroll
        for (int k = 0; k < 8; k++) {
            float xv = __shfl_sync(0xffffffffu, xb, k);
            const float* wr = W1Ts + (32 + k) * NPAD + L;
#pragma unroll
            for (int j = 0; j < NJ; j++) cur[j] += xv * wr[32 * j];
        }

        // sparse recurrent part: cur += sum over active k of WhT[k,:]
        {
            int i = 0;
            for (; i + 2 <= cnt; i += 2) {
                const float* wr0 = g_WhT + (int)alr[i] * NPAD + L;
                const float* wr1 = g_WhT + (int)alr[i + 1] * NPAD + L;
#pragma unroll
                for (int j = 0; j < NJ; j++) cur[j] += wr0[32 * j];
#pragma unroll
                for (int j = 0; j < NJ; j++) cur[j] += wr1[32 * j];
            }
            if (i < cnt) {
                const float* wr0 = g_WhT + (int)alr[i] * NPAD + L;
#pragma unroll
                for (int j = 0; j < NJ; j++) cur[j] += wr0[32 * j];
            }
        }
        __syncwarp();

        // ---- LIF 1 + rebuild active list (sorted, deterministic) ----
        int newcnt = 0;
#pragma unroll
        for (int j = 0; j < NJ; j++) {
            float v = v1[j];
            v = v + (cur[j] - v) * 0.5f;       // v + (cur - v)/tau, tau=2
            bool s = (v >= 1.0f);              // H(v - vth), vth=1
            v1[j] = s ? 0.0f : v;              // hard reset
            unsigned m = __ballot_sync(0xffffffffu, s);
            if (s) {
                int pos = newcnt + __popc(m & ((1u << L) - 1u));
                alr[pos] = (unsigned short)(L + 32 * j);
            }
            newcnt += __popc(m);
        }
        cnt = newcnt;
        __syncwarp();

        // ================= layer 2 =================
        float cur2[NJ];
#pragma unroll
        for (int j = 0; j < NJ; j++) cur2[j] = b2s[L + 32 * j];
        {
            int i = 0;
            for (; i + 2 <= cnt; i += 2) {
                const float* wr0 = g_W2T + (int)alr[i] * NPAD + L;
                const float* wr1 = g_W2T + (int)alr[i + 1] * NPAD + L;
#pragma unroll
                for (int j = 0; j < NJ; j++) cur2[j] += wr0[32 * j];
#pragma unroll
                for (int j = 0; j < NJ; j++) cur2[j] += wr1[32 * j];
            }
            if (i < cnt) {
                const float* wr0 = g_W2T + (int)alr[i] * NPAD + L;
#pragma unroll
                for (int j = 0; j < NJ; j++) cur2[j] += wr0[32 * j];
            }
        }
        __syncwarp();

        // ---- LIF 2 + output accumulation ----
        if (L < OUT_DIM) outacc += b3s[L];
#pragma unroll
        for (int j = 0; j < NJ; j++) {
            float v = v2[j];
            v = v + (cur2[j] - v) * 0.5f;
            bool s = (v >= 1.0f);
            v2[j] = s ? 0.0f : v;
            unsigned m = __ballot_sync(0xffffffffu, s);
            while (m) {
                int bpos = __ffs(m) - 1;
                m &= m - 1;
                int n2 = bpos + 32 * j;
                if (L < OUT_DIM) outacc += W3Ts[n2 * OUT_DIM + L];
            }
        }
    }

    if (L < OUT_DIM) out[row * OUT_DIM + L] = outacc;
}

extern "C" void kernel_launch(void* const* d_in, const int* in_sizes, int n_in,
                              void* d_out, int out_size) {
    const float* x  = (const float*)d_in[0];
    const float* W1 = (const float*)d_in[1];
    const float* b1 = (const float*)d_in[2];
    const float* Wh = (const float*)d_in[3];
    const float* bh = (const float*)d_in[4];
    const float* W2 = (const float*)d_in[5];
    const float* b2 = (const float*)d_in[6];
    const float* W3 = (const float*)d_in[7];
    const float* b3 = (const float*)d_in[8];
    float* out = (float*)d_out;

    // weight transpose/pad prep
    {
        int total = HID * NPAD;
        int threads = 256;
        int blocks = (total + threads - 1) / threads;
        prep_kernel<<<blocks, threads>>>(Wh, W2);
    }

    // main persistent SNN kernel
    size_t smem = (size_t)IN_DIM * NPAD * 4      // W1Ts
                + (size_t)NPAD * OUT_DIM * 4     // W3Ts
                + NPAD * 4                        // bsum
                + NPAD * 4                        // b2s
                + 16 * 4                          // b3s
                + (size_t)WARPS_PER_BLK * AL_STRIDE * 2; // active lists
    cudaFuncSetAttribute(snn_kernel, cudaFuncAttributeMaxDynamicSharedMemorySize,
                         (int)smem);
    snn_kernel<<<NUM_BLKS, THREADS_PER_BLK, smem>>>(x, W1, b1, bh, b2, W3, b3, out);
}

// round 3
// speedup vs baseline: 1.5509x; 1.5509x over previous
#include <cuda_runtime.h>
#include <cstdint>
#include <cstddef>

// Problem constants
#define T_STEPS   101
#define B_SZ      16384
#define IN_DIM    40
#define HID       300
#define NPAD      320
#define NJ        10          // NPAD / 32
#define OUT_DIM   12

#define WARPS_PER_BLK   8
#define THREADS_PER_BLK 256
#define ROWS_PER_WARP   2
#define ROWS_PER_BLK    (WARPS_PER_BLK * ROWS_PER_WARP)   // 16
#define NUM_BLKS        (B_SZ / ROWS_PER_BLK)             // 1024
#define AL_STRIDE       304

// Transposed, padded recurrent/ff weights (L2-resident, 384KB each)
__device__ float g_WhT[HID * NPAD];
__device__ float g_W2T[HID * NPAD];

__global__ void prep_kernel(const float* __restrict__ Wh,
                            const float* __restrict__ W2) {
    int idx = blockIdx.x * blockDim.x + threadIdx.x;
    const int total = HID * NPAD;
    if (idx < total) {
        int k = idx / NPAD;
        int i = idx % NPAD;
        float wh = 0.0f, w2 = 0.0f;
        if (i < HID) {
            wh = Wh[i * HID + k];
            w2 = W2[i * HID + k];
        }
        g_WhT[idx] = wh;
        g_W2T[idx] = w2;
    }
}

// One warp owns TWO batch rows for all T steps. W1^T smem bytes are shared
// across both rows (halves L1 traffic per row). Layer-2 spikes accumulate
// into packed 8-bit counters; out = counts @ W3^T + 101*b3 at the end.
__global__ void __launch_bounds__(THREADS_PER_BLK, 2)
snn_kernel(const float* __restrict__ x,
           const float* __restrict__ W1,
           const float* __restrict__ b1,
           const float* __restrict__ bh,
           const float* __restrict__ b2,
           const float* __restrict__ W3,
           const float* __restrict__ b3,
           float* __restrict__ out) {
    extern __shared__ char smem_raw[];
    float* W1Ts = (float*)smem_raw;                     // [IN_DIM][NPAD]
    float* W3Ts = W1Ts + IN_DIM * NPAD;                 // [NPAD][OUT_DIM]
    unsigned short* al = (unsigned short*)(W3Ts + NPAD * OUT_DIM);
    // al: [ROWS_PER_BLK][AL_STRIDE], 4B-aligned (NPAD*OUT_DIM floats precede)

    const int tid = threadIdx.x;

    // ---- cooperative smem init ----
    for (int idx = tid; idx < IN_DIM * NPAD; idx += THREADS_PER_BLK) {
        int k = idx / NPAD;
        int h = idx % NPAD;
        W1Ts[idx] = (h < HID) ? W1[h * IN_DIM + k] : 0.0f;
    }
    for (int idx = tid; idx < NPAD * OUT_DIM; idx += THREADS_PER_BLK) {
        int n = idx / OUT_DIM;
        int o = idx % OUT_DIM;
        W3Ts[idx] = (n < HID) ? W3[o * HID + n] : 0.0f;
    }
    __syncthreads();

    const int w  = tid >> 5;
    const int L  = tid & 31;
    const int row0 = (blockIdx.x * WARPS_PER_BLK + w) * ROWS_PER_WARP;
    const int row1 = row0 + 1;
    unsigned short* al0 = al + (w * 2) * AL_STRIDE;
    unsigned short* al1 = al0 + AL_STRIDE;

    // biases in registers (shared by both rows)
    float bs1[NJ], b2r[NJ];
#pragma unroll
    for (int j = 0; j < NJ; j++) {
        int n = L + 32 * j;
        bs1[j] = (n < HID) ? (b1[n] + bh[n]) : 0.0f;
        b2r[j] = (n < HID) ? b2[n] : 0.0f;
    }

    // LIF states
    float v1a[NJ], v1b[NJ], v2a[NJ], v2b[NJ];
#pragma unroll
    for (int j = 0; j < NJ; j++) {
        v1a[j] = 0.0f; v1b[j] = 0.0f; v2a[j] = 0.0f; v2b[j] = 0.0f;
    }
    // packed 8-bit layer-2 spike counters (4 per u32; counts <= 101)
    unsigned c2p0[3] = {0u, 0u, 0u};
    unsigned c2p1[3] = {0u, 0u, 0u};
    int cnt0 = 0, cnt1 = 0;

    const float* xr0 = x + (size_t)row0 * IN_DIM;
    const float* xr1 = x + (size_t)row1 * IN_DIM;
    const size_t xstep = (size_t)B_SZ * IN_DIM;

#pragma unroll 1
    for (int t = 0; t < T_STEPS; t++) {
        // load x rows (IN_DIM = 40: 32 + 8)
        float xa0 = xr0[L];
        float xb0 = (L < 8) ? xr0[32 + L] : 0.0f;
        float xa1 = xr1[L];
        float xb1 = (L < 8) ? xr1[32 + L] : 0.0f;
        xr0 += xstep; xr1 += xstep;

        // ---------- layer-1 current: bias + dense x@W1^T ----------
        float cur0[NJ], cur1[NJ];
#pragma unroll
        for (int j = 0; j < NJ; j++) { cur0[j] = bs1[j]; cur1[j] = bs1[j]; }

#pragma unroll 4
        for (int k = 0; k < 32; k++) {
            float xv0 = __shfl_sync(0xffffffffu, xa0, k);
            float xv1 = __shfl_sync(0xffffffffu, xa1, k);
            const float* wr = W1Ts + k * NPAD + L;
#pragma unroll
            for (int j = 0; j < NJ; j++) {
                float wv = wr[32 * j];
                cur0[j] = fmaf(xv0, wv, cur0[j]);
                cur1[j] = fmaf(xv1, wv, cur1[j]);
            }
        }
#pragma unroll
        for (int k = 0; k < 8; k++) {
            float xv0 = __shfl_sync(0xffffffffu, xb0, k);
            float xv1 = __shfl_sync(0xffffffffu, xb1, k);
            const float* wr = W1Ts + (32 + k) * NPAD + L;
#pragma unroll
            for (int j = 0; j < NJ; j++) {
                float wv = wr[32 * j];
                cur0[j] = fmaf(xv0, wv, cur0[j]);
                cur1[j] = fmaf(xv1, wv, cur1[j]);
            }
        }

        // ---------- sparse recurrent gathers (prev-step spike lists) ----------
        {
            int i = 0;
            for (; i + 2 <= cnt0; i += 2) {
                const float* wr0 = g_WhT + (int)al0[i] * NPAD + L;
                const float* wr1 = g_WhT + (int)al0[i + 1] * NPAD + L;
#pragma unroll
                for (int j = 0; j < NJ; j++) cur0[j] += wr0[32 * j];
#pragma unroll
                for (int j = 0; j < NJ; j++) cur0[j] += wr1[32 * j];
            }
            if (i < cnt0) {
                const float* wr0 = g_WhT + (int)al0[i] * NPAD + L;
#pragma unroll
                for (int j = 0; j < NJ; j++) cur0[j] += wr0[32 * j];
            }
        }
        {
            int i = 0;
            for (; i + 2 <= cnt1; i += 2) {
                const float* wr0 = g_WhT + (int)al1[i] * NPAD + L;
                const float* wr1 = g_WhT + (int)al1[i + 1] * NPAD + L;
#pragma unroll
                for (int j = 0; j < NJ; j++) cur1[j] += wr0[32 * j];
#pragma unroll
                for (int j = 0; j < NJ; j++) cur1[j] += wr1[32 * j];
            }
            if (i < cnt1) {
                const float* wr0 = g_WhT + (int)al1[i] * NPAD + L;
#pragma unroll
                for (int j = 0; j < NJ; j++) cur1[j] += wr0[32 * j];
            }
        }
        __syncwarp();   // gathers (readers of old lists) done before rebuild

        // ---------- LIF 1 + rebuild spike lists ----------
        {
            int nc = 0;
#pragma unroll
            for (int j = 0; j < NJ; j++) {
                float v = v1a[j];
                v = v + (cur0[j] - v) * 0.5f;
                bool s = (v >= 1.0f);
                v1a[j] = s ? 0.0f : v;
                unsigned m = __ballot_sync(0xffffffffu, s);
                if (s) {
                    int pos = nc + __popc(m & ((1u << L) - 1u));
                    al0[pos] = (unsigned short)(L + 32 * j);
                }
                nc += __popc(m);
            }
            cnt0 = nc;
        }
        {
            int nc = 0;
#pragma unroll
            for (int j = 0; j < NJ; j++) {
                float v = v1b[j];
                v = v + (cur1[j] - v) * 0.5f;
                bool s = (v >= 1.0f);
                v1b[j] = s ? 0.0f : v;
                unsigned m = __ballot_sync(0xffffffffu, s);
                if (s) {
                    int pos = nc + __popc(m & ((1u << L) - 1u));
                    al1[pos] = (unsigned short)(L + 32 * j);
                }
                nc += __popc(m);
            }
            cnt1 = nc;
        }
        __syncwarp();

        // ---------- layer 2: gather W2^T with the new lists ----------
#pragma unroll
        for (int j = 0; j < NJ; j++) { cur0[j] = b2r[j]; cur1[j] = b2r[j]; }
        {
            int i = 0;
            for (; i + 2 <= cnt0; i += 2) {
                const float* wr0 = g_W2T + (int)al0[i] * NPAD + L;
                const float* wr1 = g_W2T + (int)al0[i + 1] * NPAD + L;
#pragma unroll
                for (int j = 0; j < NJ; j++) cur0[j] += wr0[32 * j];
#pragma unroll
                for (int j = 0; j < NJ; j++) cur0[j] += wr1[32 * j];
            }
            if (i < cnt0) {
                const float* wr0 = g_W2T + (int)al0[i] * NPAD + L;
#pragma unroll
                for (int j = 0; j < NJ; j++) cur0[j] += wr0[32 * j];
            }
        }
        {
            int i = 0;
            for (; i + 2 <= cnt1; i += 2) {
                const float* wr0 = g_W2T + (int)al1[i] * NPAD + L;
                const float* wr1 = g_W2T + (int)al1[i + 1] * NPAD + L;
#pragma unroll
                for (int j = 0; j < NJ; j++) cur1[j] += wr0[32 * j];
#pragma unroll
                for (int j = 0; j < NJ; j++) cur1[j] += wr1[32 * j];
            }
            if (i < cnt1) {
                const float* wr0 = g_W2T + (int)al1[i] * NPAD + L;
#pragma unroll
                for (int j = 0; j < NJ; j++) cur1[j] += wr0[32 * j];
            }
        }

        // ---------- LIF 2: count spikes (packed 8-bit counters) ----------
#pragma unroll
        for (int j = 0; j < NJ; j++) {
            float v = v2a[j];
            v = v + (cur0[j] - v) * 0.5f;
            bool s = (v >= 1.0f);
            v2a[j] = s ? 0.0f : v;
            c2p0[j >> 2] += s ? (1u << (8 * (j & 3))) : 0u;
        }
#pragma unroll
        for (int j = 0; j < NJ; j++) {
            float v = v2b[j];
            v = v + (cur1[j] - v) * 0.5f;
            bool s = (v >= 1.0f);
            v2b[j] = s ? 0.0f : v;
            c2p1[j >> 2] += s ? (1u << (8 * (j & 3))) : 0u;
        }
    }

    // ---------- finalize: out[row] = counts @ W3^T + 101*b3 ----------
    for (int r = 0; r < 2; r++) {
        const unsigned* cp = (r == 0) ? c2p0 : c2p1;
        const int row = (r == 0) ? row0 : row1;
        float acc[OUT_DIM];
#pragma unroll
        for (int o = 0; o < OUT_DIM; o++) acc[o] = 0.0f;
#pragma unroll
        for (int j = 0; j < NJ; j++) {
            float c = (float)((cp[j >> 2] >> (8 * (j & 3))) & 255u);
            const float* wr = W3Ts + (L + 32 * j) * OUT_DIM;
#pragma unroll
            for (int o = 0; o < OUT_DIM; o++) acc[o] = fmaf(c, wr[o], acc[o]);
        }
#pragma unroll
        for (int o = 0; o < OUT_DIM; o++) {
            float s = acc[o];
            s += __shfl_xor_sync(0xffffffffu, s, 16);
            s += __shfl_xor_sync(0xffffffffu, s, 8);
            s += __shfl_xor_sync(0xffffffffu, s, 4);
            s += __shfl_xor_sync(0xffffffffu, s, 2);
            s += __shfl_xor_sync(0xffffffffu, s, 1);
            if (L == 0) out[row * OUT_DIM + o] = s + 101.0f * b3[o];
        }
    }
}

extern "C" void kernel_launch(void* const* d_in, const int* in_sizes, int n_in,
                              void* d_out, int out_size) {
    const float* x  = (const float*)d_in[0];
    const float* W1 = (const float*)d_in[1];
    const float* b1 = (const float*)d_in[2];
    const float* Wh = (const float*)d_in[3];
    const float* bh = (const float*)d_in[4];
    const float* W2 = (const float*)d_in[5];
    const float* b2 = (const float*)d_in[6];
    const float* W3 = (const float*)d_in[7];
    const float* b3 = (const float*)d_in[8];
    float* out = (float*)d_out;

    {
        int total = HID * NPAD;
        int threads = 256;
        int blocks = (total + threads - 1) / threads;
        prep_kernel<<<blocks, threads>>>(Wh, W2);
    }

    size_t smem = (size_t)IN_DIM * NPAD * 4           // W1Ts
                + (size_t)NPAD * OUT_DIM * 4          // W3Ts
                + (size_t)ROWS_PER_BLK * AL_STRIDE * 2;
    cudaFuncSetAttribute(snn_kernel, cudaFuncAttributeMaxDynamicSharedMemorySize,
                         (int)smem);
    snn_kernel<<<NUM_BLKS, THREADS_PER_BLK, smem>>>(x, W1, b1, bh, b2, W3, b3, out);
}